// round 8
// baseline (speedup 1.0000x reference)
#include <cuda_runtime.h>

#define BB 16
#define NN 1024
#define DD 1024   // D2H
#define UU 512
#define TOK (BB * NN)

#define UCH  32                     // u-chunks (one block each)
#define UC   (UU / UCH)             // 16 u per chunk
#define PRO  UCH                    // 32 prologue blocks (float4 over d)
#define ROW_BLOCKS (TOK / 16)       // 1024 (16 rows per block, warp per 2 rows)
#define OUT_BLOCKS (TOK / 8)        // 2048 (8 rows per block)
#define RB_PER_BATCH (NN / 16)      // 64 row-blocks per batch

// Scratch (no device allocation allowed; rewritten every launch).
__device__ float g_ph[UCH * DD];
__device__ float g_pm[UCH * DD];
__device__ float g_vh[DD];
__device__ float g_vm[DD];
__device__ float g_const;
__device__ float g_sH[TOK];
__device__ float g_sM[TOK];
__device__ int   g_done[BB];

// ---------------------------------------------------------------------------
// Stage 1: v partials.  32 blocks x 256 threads; each thread owns 4 d's
// (float4) and 16 u's -> 32 independent float4 loads in flight per thread,
// the whole 4 MB W read is one MLP wave.  Block 0 zeroes g_done.
// ---------------------------------------------------------------------------
__global__ void k_pre(const float* __restrict__ Wh,
                      const float* __restrict__ Wm,
                      const float* __restrict__ wout) {
    int t = threadIdx.x;
    if (blockIdx.x == 0 && t < BB) g_done[t] = 0;

    int u0 = blockIdx.x * UC;
    const float4* Wh4 = reinterpret_cast<const float4*>(Wh);
    const float4* Wm4 = reinterpret_cast<const float4*>(Wm);
    float4 ah = make_float4(0.f, 0.f, 0.f, 0.f);
    float4 am = make_float4(0.f, 0.f, 0.f, 0.f);
#pragma unroll
    for (int i = 0; i < UC; ++i) {
        float  w = __ldg(&wout[u0 + i]);
        float4 a = Wh4[(size_t)(u0 + i) * (DD / 4) + t];
        float4 b = Wm4[(size_t)(u0 + i) * (DD / 4) + t];
        ah.x = fmaf(a.x, w, ah.x); ah.y = fmaf(a.y, w, ah.y);
        ah.z = fmaf(a.z, w, ah.z); ah.w = fmaf(a.w, w, ah.w);
        am.x = fmaf(b.x, w, am.x); am.y = fmaf(b.y, w, am.y);
        am.z = fmaf(b.z, w, am.z); am.w = fmaf(b.w, w, am.w);
    }
    reinterpret_cast<float4*>(g_ph)[blockIdx.x * (DD / 4) + t] = ah;
    reinterpret_cast<float4*>(g_pm)[blockIdx.x * (DD / 4) + t] = am;
}

// ---------------------------------------------------------------------------
// Stage 2: blocks 0..3 fold the 32 partials into v_h/v_m (256 d each);
// block 4 computes g_const = (b_h + b_m) . w_out + b_out.
// ---------------------------------------------------------------------------
__global__ void k_finish(const float* __restrict__ bh,
                         const float* __restrict__ bm,
                         const float* __restrict__ wout,
                         const float* __restrict__ bout) {
    int t = threadIdx.x;
    if (blockIdx.x < 4) {
        int d = blockIdx.x * 256 + t;
        float ah = 0.f, am = 0.f;
#pragma unroll
        for (int c = 0; c < UCH; ++c) {
            ah += g_ph[c * DD + d];
            am += g_pm[c * DD + d];
        }
        g_vh[d] = ah;
        g_vm[d] = am;
    } else {
        __shared__ float red[8];
        float acc = (bh[t] + bm[t]) * wout[t]
                  + (bh[t + 256] + bm[t + 256]) * wout[t + 256];
#pragma unroll
        for (int o = 16; o > 0; o >>= 1)
            acc += __shfl_down_sync(0xffffffffu, acc, o);
        if ((t & 31) == 0) red[t >> 5] = acc;
        __syncthreads();
        if (t < 8) {
            acc = red[t];
#pragma unroll
            for (int o = 4; o > 0; o >>= 1)
                acc += __shfl_down_sync(0x000000ffu, acc, o);
            if (t == 0) g_const = acc + bout[0];
        }
    }
}

// ---------------------------------------------------------------------------
// Stage 3 (fused row+out pipeline).
// Producer: warp per TWO rows — 16 x float4 prefetched, v loads SHARED
// between the rows (16 LDG/row instead of 24), reduce/bar/atomic tail
// amortized 2x.  Consumer: unchanged batch-gated 8-row writer.
// ---------------------------------------------------------------------------
__global__ void __launch_bounds__(256, 3)
k_main(const float* __restrict__ x, float* __restrict__ out) {
    int bid = blockIdx.x;
    int t   = threadIdx.x;

    if (bid < ROW_BLOCKS) {
        // ---- producer: 2 rows per warp ----
        int warp = t >> 5;
        int lane = t & 31;
        int r0   = bid * 16 + warp * 2;     // rows r0, r0+1
        const float4* x0  = reinterpret_cast<const float4*>(x + (size_t)r0 * DD);
        const float4* x1  = x0 + (DD / 4);
        const float4* vh4 = reinterpret_cast<const float4*>(g_vh);
        const float4* vm4 = reinterpret_cast<const float4*>(g_vm);

        float4 xa[8], xb[8];
#pragma unroll
        for (int i = 0; i < 8; ++i) xa[i] = __ldcs(&x0[lane + 32 * i]);
#pragma unroll
        for (int i = 0; i < 8; ++i) xb[i] = __ldcs(&x1[lane + 32 * i]);

        float ah0 = 0.f, am0 = 0.f, ah1 = 0.f, am1 = 0.f;
#pragma unroll
        for (int i = 0; i < 8; ++i) {
            int idx = lane + 32 * i;
            float4 h = vh4[idx];
            float4 m = vm4[idx];
            ah0 = fmaf(xa[i].x, h.x, fmaf(xa[i].y, h.y, fmaf(xa[i].z, h.z, fmaf(xa[i].w, h.w, ah0))));
            am0 = fmaf(xa[i].x, m.x, fmaf(xa[i].y, m.y, fmaf(xa[i].z, m.z, fmaf(xa[i].w, m.w, am0))));
            ah1 = fmaf(xb[i].x, h.x, fmaf(xb[i].y, h.y, fmaf(xb[i].z, h.z, fmaf(xb[i].w, h.w, ah1))));
            am1 = fmaf(xb[i].x, m.x, fmaf(xb[i].y, m.y, fmaf(xb[i].z, m.z, fmaf(xb[i].w, m.w, am1))));
        }
#pragma unroll
        for (int o = 16; o > 0; o >>= 1) {
            ah0 += __shfl_xor_sync(0xffffffffu, ah0, o);
            am0 += __shfl_xor_sync(0xffffffffu, am0, o);
            ah1 += __shfl_xor_sync(0xffffffffu, ah1, o);
            am1 += __shfl_xor_sync(0xffffffffu, am1, o);
        }
        if (lane == 0) {
            g_sH[r0]     = ah0;
            g_sH[r0 + 1] = ah1;
            g_sM[r0]     = am0;
            g_sM[r0 + 1] = am1;
            __threadfence();                        // release
        }
        __syncthreads();
        if (t == 0) atomicAdd(&g_done[bid >> 6], 1);   // RB_PER_BATCH = 64
    } else {
        // ---- consumer: write 8 output rows of one batch ----
        int ob = bid - ROW_BLOCKS;
        int i0 = ob * 8;            // global row base (b*NN + i)
        int b  = i0 >> 10;          // NN = 1024

        if (t == 0) {
            while (*(volatile int*)&g_done[b] < RB_PER_BATCH)
                __nanosleep(128);
            __threadfence();        // acquire
        }
        __syncthreads();

        float4 m = reinterpret_cast<const float4*>(g_sM + (size_t)b * NN)[t];
        float  c = g_const;
        float4 h0 = reinterpret_cast<const float4*>(g_sH + i0)[0];
        float4 h1 = reinterpret_cast<const float4*>(g_sH + i0)[1];
        float base[8] = {h0.x + c, h0.y + c, h0.z + c, h0.w + c,
                         h1.x + c, h1.y + c, h1.z + c, h1.w + c};
#pragma unroll
        for (int r = 0; r < 8; ++r) {
            __stcs(reinterpret_cast<float4*>(out + (size_t)(i0 + r) * NN) + t,
                   make_float4(base[r] + m.x, base[r] + m.y,
                               base[r] + m.z, base[r] + m.w));
        }
    }
}

extern "C" void kernel_launch(void* const* d_in, const int* in_sizes, int n_in,
                              void* d_out, int out_size) {
    const float* x    = (const float*)d_in[0];
    const float* Wh   = (const float*)d_in[1];
    const float* bh   = (const float*)d_in[2];
    const float* Wm   = (const float*)d_in[3];
    const float* bm   = (const float*)d_in[4];
    const float* wout = (const float*)d_in[5];
    const float* bout = (const float*)d_in[6];
    float* out = (float*)d_out;

    k_pre<<<PRO, 256>>>(Wh, Wm, wout);
    k_finish<<<5, 256>>>(bh, bm, wout, bout);
    k_main<<<ROW_BLOCKS + OUT_BLOCKS, 256>>>(x, out);
}

// round 9
// speedup vs baseline: 1.0069x; 1.0069x over previous
#include <cuda_runtime.h>

#define BB 16
#define NN 1024
#define DD 1024   // D2H
#define UU 512
#define TOK (BB * NN)

#define DGRP 4                      // d-groups of 256
#define UCH  32                     // u-chunks
#define UC   (UU / UCH)             // 16 u per chunk
#define PRO  (DGRP * UCH)           // 128 prologue blocks
#define ROW_BLOCKS (TOK / 16)       // 1024 (16 rows per block, warp per 2 rows)
#define OUT_BLOCKS (TOK / 8)        // 2048
#define RB_PER_BATCH (NN / 16)      // 64 row-blocks per batch

#define GDC_LAUNCH() asm volatile("griddepcontrol.launch_dependents;")
#define GDC_WAIT()   asm volatile("griddepcontrol.wait;" ::: "memory")

// Scratch (no device allocation allowed; rewritten every launch).
__device__ float g_ph[UCH * DD];
__device__ float g_pm[UCH * DD];
__device__ float g_vh[DD];
__device__ float g_vm[DD];
__device__ float g_const;
__device__ float g_sH[TOK];
__device__ float g_sM[TOK];
__device__ int   g_done[BB];

// ---------------------------------------------------------------------------
// Stage 1: v partials (R7 proven geometry: 128 blocks x 256 thr, scalar).
// Fires launch_dependents immediately so k_finish/k_main can launch early.
// Block 0 zeroes the g_done counters for this replay.
// ---------------------------------------------------------------------------
__global__ void k_pre(const float* __restrict__ Wh,
                      const float* __restrict__ Wm,
                      const float* __restrict__ wout) {
    GDC_LAUNCH();
    int t = threadIdx.x;
    if (blockIdx.x == 0 && t < BB) g_done[t] = 0;

    int d  = (blockIdx.x & (DGRP - 1)) * 256 + t;
    int uc = blockIdx.x >> 2;               // / DGRP, 0..31
    int u0 = uc * UC;
    float ah = 0.f, am = 0.f;
#pragma unroll
    for (int i = 0; i < UC; ++i) {
        float w = __ldg(&wout[u0 + i]);
        ah = fmaf(Wh[(size_t)(u0 + i) * DD + d], w, ah);
        am = fmaf(Wm[(size_t)(u0 + i) * DD + d], w, am);
    }
    g_ph[uc * DD + d] = ah;
    g_pm[uc * DD + d] = am;
}

// ---------------------------------------------------------------------------
// Stage 2 (PDL): launches while k_pre runs.  Reduce blocks wait for k_pre
// before touching g_ph; const block proceeds immediately (independent data).
// ---------------------------------------------------------------------------
__global__ void k_finish(const float* __restrict__ bh,
                         const float* __restrict__ bm,
                         const float* __restrict__ wout,
                         const float* __restrict__ bout) {
    GDC_LAUNCH();
    int t = threadIdx.x;
    if (blockIdx.x < 4) {
        GDC_WAIT();                 // k_pre's partials must be complete
        int d = blockIdx.x * 256 + t;
        float ah = 0.f, am = 0.f;
#pragma unroll
        for (int c = 0; c < UCH; ++c) {
            ah += g_ph[c * DD + d];
            am += g_pm[c * DD + d];
        }
        g_vh[d] = ah;
        g_vm[d] = am;
    } else {
        __shared__ float red[8];
        float acc = (bh[t] + bm[t]) * wout[t]
                  + (bh[t + 256] + bm[t + 256]) * wout[t + 256];
#pragma unroll
        for (int o = 16; o > 0; o >>= 1)
            acc += __shfl_down_sync(0xffffffffu, acc, o);
        if ((t & 31) == 0) red[t >> 5] = acc;
        __syncthreads();
        if (t < 8) {
            acc = red[t];
#pragma unroll
            for (int o = 4; o > 0; o >>= 1)
                acc += __shfl_down_sync(0x000000ffu, acc, o);
            if (t == 0) g_const = acc + bout[0];
        }
    }
}

// ---------------------------------------------------------------------------
// Stage 3 (PDL): launches while k_pre/k_finish run.  Row blocks prefetch
// their x tiles BEFORE griddepcontrol.wait -> the 64 MB x stream hides the
// whole v-precompute.  Producer: warp per 2 rows (shared v loads, amortized
// tail).  Consumer: batch-gated 8-row writer (waits first: guarantees the
// g_done zeroing in k_pre is visible, removing the replay race).
// ---------------------------------------------------------------------------
__global__ void __launch_bounds__(256, 3)
k_main(const float* __restrict__ x, float* __restrict__ out) {
    int bid = blockIdx.x;
    int t   = threadIdx.x;

    if (bid < ROW_BLOCKS) {
        // ---- producer: 2 rows per warp ----
        int warp = t >> 5;
        int lane = t & 31;
        int r0   = bid * 16 + warp * 2;     // rows r0, r0+1
        const float4* x0  = reinterpret_cast<const float4*>(x + (size_t)r0 * DD);
        const float4* x1  = x0 + (DD / 4);
        const float4* vh4 = reinterpret_cast<const float4*>(g_vh);
        const float4* vm4 = reinterpret_cast<const float4*>(g_vm);

        float4 xa[8], xb[8];
#pragma unroll
        for (int i = 0; i < 8; ++i) xa[i] = __ldcs(&x0[lane + 32 * i]);
#pragma unroll
        for (int i = 0; i < 8; ++i) xb[i] = __ldcs(&x1[lane + 32 * i]);

        GDC_WAIT();                 // v_h/v_m ready (k_finish complete)

        float ah0 = 0.f, am0 = 0.f, ah1 = 0.f, am1 = 0.f;
#pragma unroll
        for (int i = 0; i < 8; ++i) {
            int idx = lane + 32 * i;
            float4 h = vh4[idx];
            float4 m = vm4[idx];
            ah0 = fmaf(xa[i].x, h.x, fmaf(xa[i].y, h.y, fmaf(xa[i].z, h.z, fmaf(xa[i].w, h.w, ah0))));
            am0 = fmaf(xa[i].x, m.x, fmaf(xa[i].y, m.y, fmaf(xa[i].z, m.z, fmaf(xa[i].w, m.w, am0))));
            ah1 = fmaf(xb[i].x, h.x, fmaf(xb[i].y, h.y, fmaf(xb[i].z, h.z, fmaf(xb[i].w, h.w, ah1))));
            am1 = fmaf(xb[i].x, m.x, fmaf(xb[i].y, m.y, fmaf(xb[i].z, m.z, fmaf(xb[i].w, m.w, am1))));
        }
#pragma unroll
        for (int o = 16; o > 0; o >>= 1) {
            ah0 += __shfl_xor_sync(0xffffffffu, ah0, o);
            am0 += __shfl_xor_sync(0xffffffffu, am0, o);
            ah1 += __shfl_xor_sync(0xffffffffu, ah1, o);
            am1 += __shfl_xor_sync(0xffffffffu, am1, o);
        }
        if (lane == 0) {
            g_sH[r0]     = ah0;
            g_sH[r0 + 1] = ah1;
            g_sM[r0]     = am0;
            g_sM[r0 + 1] = am1;
            __threadfence();                        // release
        }
        __syncthreads();
        if (t == 0) atomicAdd(&g_done[bid >> 6], 1);   // RB_PER_BATCH = 64
    } else {
        // ---- consumer: write 8 output rows of one batch ----
        GDC_WAIT();                 // ensures g_done zeroing is visible
        int ob = bid - ROW_BLOCKS;
        int i0 = ob * 8;            // global row base (b*NN + i)
        int b  = i0 >> 10;          // NN = 1024

        if (t == 0) {
            while (*(volatile int*)&g_done[b] < RB_PER_BATCH)
                __nanosleep(128);
            __threadfence();        // acquire
        }
        __syncthreads();

        float4 m = reinterpret_cast<const float4*>(g_sM + (size_t)b * NN)[t];
        float  c = g_const;
        float4 h0 = reinterpret_cast<const float4*>(g_sH + i0)[0];
        float4 h1 = reinterpret_cast<const float4*>(g_sH + i0)[1];
        float base[8] = {h0.x + c, h0.y + c, h0.z + c, h0.w + c,
                         h1.x + c, h1.y + c, h1.z + c, h1.w + c};
#pragma unroll
        for (int r = 0; r < 8; ++r) {
            __stcs(reinterpret_cast<float4*>(out + (size_t)(i0 + r) * NN) + t,
                   make_float4(base[r] + m.x, base[r] + m.y,
                               base[r] + m.z, base[r] + m.w));
        }
    }
}

extern "C" void kernel_launch(void* const* d_in, const int* in_sizes, int n_in,
                              void* d_out, int out_size) {
    const float* x    = (const float*)d_in[0];
    const float* Wh   = (const float*)d_in[1];
    const float* bh   = (const float*)d_in[2];
    const float* Wm   = (const float*)d_in[3];
    const float* bm   = (const float*)d_in[4];
    const float* wout = (const float*)d_in[5];
    const float* bout = (const float*)d_in[6];
    float* out = (float*)d_out;

    // k_pre: normal launch (first in chain)
    k_pre<<<PRO, 256>>>(Wh, Wm, wout);

    // k_finish + k_main: programmatic dependent launch (overlap with upstream)
    cudaLaunchAttribute attr[1];
    attr[0].id = cudaLaunchAttributeProgrammaticStreamSerialization;
    attr[0].val.programmaticStreamSerializationAllowed = 1;

    {
        cudaLaunchConfig_t cfg = {};
        cfg.gridDim  = dim3(5);
        cfg.blockDim = dim3(256);
        cfg.attrs    = attr;
        cfg.numAttrs = 1;
        cudaLaunchKernelEx(&cfg, k_finish, bh, bm, wout, bout);
    }
    {
        cudaLaunchConfig_t cfg = {};
        cfg.gridDim  = dim3(ROW_BLOCKS + OUT_BLOCKS);
        cfg.blockDim = dim3(256);
        cfg.attrs    = attr;
        cfg.numAttrs = 1;
        cudaLaunchKernelEx(&cfg, k_main, x, out);
    }
}